// round 4
// baseline (speedup 1.0000x reference)
#include <cuda_runtime.h>
#include <math.h>

#define BB 8
#define CC 64
#define NN 4096
#define TOT (BB*CC*NN)
#define NBLK 64            // n-tiles per batch in K1 (4096/64)

// Scratch (allocation-free: __device__ globals)
__device__ float g_z[TOT];                  // z = W @ x  (8 MB)
__device__ float g_psum[BB*CC*NBLK];        // per-block partial Σz   [b][o][nb]
__device__ float g_psq [BB*CC*NBLK];        // per-block partial Σz²  [b][o][nb]
__device__ float g_spart[BB*NBLK];          // per-block partial s_b
__device__ float g_scale[BB*CC];
__device__ float g_bias [BB*CC];

// ---- f32x2 packed helpers (sm_103a) ----
__device__ __forceinline__ unsigned long long ffma2(unsigned long long a,
                                                    unsigned long long b,
                                                    unsigned long long c) {
    unsigned long long d;
    asm("fma.rn.f32x2 %0, %1, %2, %3;" : "=l"(d) : "l"(a), "l"(b), "l"(c));
    return d;
}
__device__ __forceinline__ unsigned long long packdup(float v) {
    unsigned long long r;
    asm("mov.b64 %0, {%1, %2};" : "=l"(r) : "f"(v), "f"(v));
    return r;
}
__device__ __forceinline__ void unpack2(unsigned long long v, float& lo, float& hi) {
    asm("mov.b64 {%0, %1}, %2;" : "=f"(lo), "=f"(hi) : "l"(v));
}

// ============================================================================
// K1: z[b,o,n] = Σ_c W[o,c]·x[b,c,n].  Tile 64o × 64n, 256 threads, 4o×4n
// per-thread FFMA2 microtile. Also emits per-block partial Σz, Σz², and the
// tanh(w)² partial for its 64-wide n-slice (so K2 has no serial tanh loop).
// ============================================================================
__global__ __launch_bounds__(256) void k1_gemm(const float* __restrict__ x,
                                               const float* __restrict__ wvec,
                                               const float* __restrict__ W) {
    __shared__ float xs[64][64];        // xs[c][j]  (16 KB)
    __shared__ float wt[64][68];        // wt[c][o]  (17 KB, padded)
    __shared__ float sred[2];
    const int b  = blockIdx.y;
    const int nb = blockIdx.x;
    const int n0 = nb * 64;
    const int t  = threadIdx.x;

    // ---- tanh(w)² partial for this n-slice (64 elems, warps 0-1) ----
    float sp = 0.f;
    if (t < 64) {
        float vv = tanhf(wvec[b * NN + n0 + t]);
        vv = fmaxf(vv, 0.f);
        sp = vv * vv;
    }
    #pragma unroll
    for (int off = 16; off > 0; off >>= 1)
        sp += __shfl_xor_sync(0xFFFFFFFFu, sp, off);
    if (t == 0)  sred[0] = sp;
    if (t == 32) sred[1] = sp;

    // ---- load W transposed: wt[c][o] = W[o*64 + c] ----
    #pragma unroll
    for (int i = 0; i < 4096; i += 256) {
        int idx = i + t;
        wt[idx & 63][idx >> 6] = W[idx];
    }
    // ---- load x tile (float4, coalesced): 64 c-rows × 16 float4 ----
    const float4* x4 = (const float4*)(x + ((size_t)b * CC) * NN + n0);
    #pragma unroll
    for (int i = 0; i < 1024; i += 256) {
        int idx = i + t;
        int c = idx >> 4, j = idx & 15;
        ((float4*)xs[c])[j] = x4[c * (NN / 4) + j];
    }
    __syncthreads();
    if (t == 0) g_spart[b * NBLK + nb] = sred[0] + sred[1];

    const int tx = t & 15, ty = t >> 4;  // tx: n-group (4n), ty: o-group (4o)
    unsigned long long acc[4][2] = {};   // 4 o × 2 f32x2 pairs (4 n)

    #pragma unroll
    for (int c = 0; c < 64; c++) {
        float4 wv = *(const float4*)&wt[c][ty * 4];
        ulonglong2 xv = *(const ulonglong2*)&xs[c][tx * 4];
        unsigned long long wd0 = packdup(wv.x);
        unsigned long long wd1 = packdup(wv.y);
        unsigned long long wd2 = packdup(wv.z);
        unsigned long long wd3 = packdup(wv.w);
        acc[0][0] = ffma2(wd0, xv.x, acc[0][0]);
        acc[0][1] = ffma2(wd0, xv.y, acc[0][1]);
        acc[1][0] = ffma2(wd1, xv.x, acc[1][0]);
        acc[1][1] = ffma2(wd1, xv.y, acc[1][1]);
        acc[2][0] = ffma2(wd2, xv.x, acc[2][0]);
        acc[2][1] = ffma2(wd2, xv.y, acc[2][1]);
        acc[3][0] = ffma2(wd3, xv.x, acc[3][0]);
        acc[3][1] = ffma2(wd3, xv.y, acc[3][1]);
    }

    // Unpack to v[o][n]
    float v[4][4];
    #pragma unroll
    for (int i = 0; i < 4; i++) {
        unpack2(acc[i][0], v[i][0], v[i][1]);
        unpack2(acc[i][1], v[i][2], v[i][3]);
    }

    // Per-thread stats, reduce across the 16 tx lanes (stays in half-warp)
    float lsum[4], lsq[4];
    #pragma unroll
    for (int i = 0; i < 4; i++) {
        lsum[i] = (v[i][0] + v[i][1]) + (v[i][2] + v[i][3]);
        lsq[i]  = fmaf(v[i][0], v[i][0], fmaf(v[i][1], v[i][1],
                  fmaf(v[i][2], v[i][2], v[i][3] * v[i][3])));
    }
    #pragma unroll
    for (int off = 8; off > 0; off >>= 1) {
        #pragma unroll
        for (int i = 0; i < 4; i++) {
            lsum[i] += __shfl_xor_sync(0xFFFFFFFFu, lsum[i], off);
            lsq[i]  += __shfl_xor_sync(0xFFFFFFFFu, lsq[i],  off);
        }
    }
    if (tx == 0) {
        #pragma unroll
        for (int i = 0; i < 4; i++) {
            int o = ty * 4 + i;
            g_psum[(b * CC + o) * NBLK + nb] = lsum[i];
            g_psq [(b * CC + o) * NBLK + nb] = lsq[i];
        }
    }

    // Write z (16 lanes × contiguous float4 per o-row)
    float* zp = g_z + ((size_t)b * CC) * NN + n0;
    #pragma unroll
    for (int i = 0; i < 4; i++) {
        int o = ty * 4 + i;
        *(float4*)(zp + (size_t)o * NN + tx * 4) =
            make_float4(v[i][0], v[i][1], v[i][2], v[i][3]);
    }
}

// ============================================================================
// K2: reduce partials, closed-form BN -> per-(b,o) scale/bias. One block.
// ============================================================================
__global__ __launch_bounds__(512) void k2_finalize(const float* __restrict__ conv_b,
                                                   const float* __restrict__ gamma,
                                                   const float* __restrict__ beta) {
    __shared__ float s_s[BB];
    __shared__ float sZ[BB][CC];
    __shared__ float sQ[BB][CC];
    __shared__ float part[16];
    const int t = threadIdx.x;
    const int b = t >> 6, o = t & 63;

    // Phase 1: s_b = Σ_nb spart. 64 threads per batch, contiguous reads.
    {
        float acc = g_spart[b * NBLK + o];
        #pragma unroll
        for (int off = 16; off > 0; off >>= 1)
            acc += __shfl_xor_sync(0xFFFFFFFFu, acc, off);
        if ((t & 31) == 0) part[t >> 5] = acc;
    }

    // Phase 2a: reduce Σz, Σz² partials. Thread (b,o) reads 64 contiguous
    // floats from each array (float4, MLP-heavy).
    {
        const float4* p4 = (const float4*)(g_psum + (b * CC + o) * NBLK);
        const float4* q4 = (const float4*)(g_psq  + (b * CC + o) * NBLK);
        float Z = 0.f, Q = 0.f;
        #pragma unroll
        for (int i = 0; i < NBLK / 4; i++) {
            float4 a = p4[i];
            float4 c = q4[i];
            Z += (a.x + a.y) + (a.z + a.w);
            Q += (c.x + c.y) + (c.z + c.w);
        }
        sZ[b][o] = Z; sQ[b][o] = Q;
    }
    __syncthreads();
    if (t < BB) s_s[t] = part[2 * t] + part[2 * t + 1];
    __syncthreads();

    // Phase 2b: closed-form BN stats per channel o.
    if (t < CC) {
        float cb = conv_b[o];
        float alpha[BB], offv[BB];
        float mean_acc = 0.f, sq_acc = 0.f;
        #pragma unroll
        for (int bb = 0; bb < BB; bb++) {
            float s = s_s[bb];
            float a = 1.f / (1.f + (float)NN * s);
            float Z = sZ[bb][o];
            float Q = sQ[bb][o];
            float off = a * s * Z + cb;
            alpha[bb] = a; offv[bb] = off;
            mean_acc += a * Z + (float)NN * off;
            sq_acc   += a * a * Q + 2.f * a * off * Z + (float)NN * off * off;
        }
        const float inv_cnt = 1.f / (float)(BB * NN);
        float mean = mean_acc * inv_cnt;
        float var  = sq_acc * inv_cnt - mean * mean;
        float invstd = rsqrtf(var + 1e-5f);
        float g  = gamma[o] * invstd;
        float be = beta[o];
        #pragma unroll
        for (int bb = 0; bb < BB; bb++) {
            g_scale[bb * CC + o] = alpha[bb] * g;
            g_bias [bb * CC + o] = (offv[bb] - mean) * g + be;
        }
    }
}

// ============================================================================
// K3: out = relu(scale*z + bias). One block per (b,c) row; 4 indep float4/thread.
// ============================================================================
__global__ __launch_bounds__(256) void k3_epilogue(float* __restrict__ out) {
    const int row = blockIdx.x;                 // 512 rows of 4096 floats
    const float sc = g_scale[row];
    const float bi = g_bias[row];
    const float4* z = (const float4*)(g_z + (size_t)row * NN);
    float4* op = (float4*)(out + (size_t)row * NN);
    const int t = threadIdx.x;

    float4 v[4];
    #pragma unroll
    for (int i = 0; i < 4; i++) v[i] = z[t + i * 256];
    #pragma unroll
    for (int i = 0; i < 4; i++) {
        float4 r;
        r.x = fmaxf(fmaf(sc, v[i].x, bi), 0.f);
        r.y = fmaxf(fmaf(sc, v[i].y, bi), 0.f);
        r.z = fmaxf(fmaf(sc, v[i].z, bi), 0.f);
        r.w = fmaxf(fmaf(sc, v[i].w, bi), 0.f);
        op[t + i * 256] = r;
    }
}

extern "C" void kernel_launch(void* const* d_in, const int* in_sizes, int n_in,
                              void* d_out, int out_size) {
    const float* x      = (const float*)d_in[0];  // [8,64,4096,1]
    const float* w      = (const float*)d_in[1];  // [8,4096]
    const float* conv_w = (const float*)d_in[2];  // [64,64,1,1]
    const float* conv_b = (const float*)d_in[3];  // [64]
    const float* gamma  = (const float*)d_in[4];  // [64]
    const float* beta   = (const float*)d_in[5];  // [64]
    float* out = (float*)d_out;

    k1_gemm<<<dim3(NBLK, BB), 256>>>(x, w, conv_w);
    k2_finalize<<<1, 512>>>(conv_b, gamma, beta);
    k3_epilogue<<<BB * CC, 256>>>(out);
}